// round 1
// baseline (speedup 1.0000x reference)
#include <cuda_runtime.h>
#include <cstdint>

// Problem constants
#define BB 8
#define NN 4096
#define MM 1024
#define KK 32
#define CF 64
#define C0IN 67
#define C0 64
#define C1 64
#define C2 128
#define STOT (BB*MM*KK)          // 262144 samples
#define EPSBN 1e-5f

// ---------------- scratch (device globals; no cudaMalloc allowed) ----------
__device__ int   g_idx[STOT];
__device__ float g_xT[BB*NN*CF];            // x transposed to (B,N,C)
__device__ float g_h0[(size_t)C0*STOT];     // pre-BN layer0 out, [C][S]
__device__ float g_h1[(size_t)C1*STOT];
__device__ float g_h2[(size_t)C2*STOT];
__device__ float g_psum[C2*32];
__device__ float g_psq [C2*32];
__device__ float g_scale[C2];
__device__ float g_shift[C2];

// ---------------- transpose x: (B,C,N) -> (B,N,C) --------------------------
__global__ void k_transpose(const float* __restrict__ x) {
    __shared__ float t[32][33];
    int b  = blockIdx.z;
    int c0 = blockIdx.y * 32;
    int n0 = blockIdx.x * 32;
    int tx = threadIdx.x, ty = threadIdx.y;
#pragma unroll
    for (int r = ty; r < 32; r += 8)
        t[r][tx] = x[(size_t)b*CF*NN + (size_t)(c0 + r)*NN + n0 + tx];
    __syncthreads();
#pragma unroll
    for (int r = ty; r < 32; r += 8)
        g_xT[((size_t)b*NN + n0 + r)*CF + c0 + tx] = t[tx][r];
}

// ---------------- copy q into the head of d_out -----------------------------
__global__ void k_copyq(const float* __restrict__ q, float* __restrict__ out) {
    int i = blockIdx.x * 256 + threadIdx.x;   // exactly 24576 threads launched
    out[i] = q[i];
}

// ---------------- ball query ------------------------------------------------
// warp-per-query; first-K in-ball indices in ascending order; pad with first
// found (or 0 if none). Threshold matches JAX: float32(0.04).
__global__ void k_ballquery(const float* __restrict__ p, const float* __restrict__ q) {
    extern __shared__ float sp[];                 // NN*3 floats
    int* sfound = (int*)(sp + NN*3);              // [8][KK]
    const int b    = blockIdx.y;
    const int warp = threadIdx.x >> 5;
    const int lane = threadIdx.x & 31;
    const int m    = blockIdx.x * 8 + warp;

    const float* pb = p + (size_t)b * NN * 3;
    for (int i = threadIdx.x; i < NN*3; i += blockDim.x) sp[i] = pb[i];
    __syncthreads();

    const float qx = q[((size_t)b*MM + m)*3 + 0];
    const float qy = q[((size_t)b*MM + m)*3 + 1];
    const float qz = q[((size_t)b*MM + m)*3 + 2];
    const float R2 = 0.04f;   // float32(0.2**2) as JAX weak-type promotes it

    int cnt = 0;
    for (int j0 = 0; j0 < NN; j0 += 32) {
        int j = j0 + lane;
        float dx = __fadd_rn(sp[3*j+0], -qx);
        float dy = __fadd_rn(sp[3*j+1], -qy);
        float dz = __fadd_rn(sp[3*j+2], -qz);
        // no FMA contraction: match JAX (sum of separately-rounded squares)
        float d2 = __fadd_rn(__fadd_rn(__fmul_rn(dx,dx), __fmul_rn(dy,dy)), __fmul_rn(dz,dz));
        bool in = d2 < R2;
        unsigned bal = __ballot_sync(0xffffffffu, in);
        if (in) {
            int slot = cnt + __popc(bal & ((1u << lane) - 1u));
            if (slot < KK) sfound[warp*KK + slot] = j;
        }
        cnt += __popc(bal);
        if (cnt >= KK) break;
    }
    __syncwarp();
    int v;
    if (lane < cnt)      v = sfound[warp*KK + lane];
    else if (cnt > 0)    v = sfound[warp*KK];
    else                 v = 0;
    g_idx[((size_t)b*MM + m)*KK + lane] = v;
}

// ---------------- rank-1 accumulate helper ----------------------------------
__device__ __forceinline__ void rank1(float4 (&acc)[16], const float4* __restrict__ wr, float v) {
#pragma unroll
    for (int i = 0; i < 16; i++) {
        acc[i].x = fmaf(v, wr[i].x, acc[i].x);
        acc[i].y = fmaf(v, wr[i].y, acc[i].y);
        acc[i].z = fmaf(v, wr[i].z, acc[i].z);
        acc[i].w = fmaf(v, wr[i].w, acc[i].w);
    }
}

// ---------------- layer 0: gather + linear (67 -> 64) -----------------------
__global__ void __launch_bounds__(256)
k_layer0(const float* __restrict__ p, const float* __restrict__ q,
         const float* __restrict__ W, const float* __restrict__ bias) {
    __shared__ float Wsm[C0IN * 64];
    for (int i = threadIdx.x; i < C0IN*64; i += 256) {
        int c = i >> 6, o = i & 63;
        Wsm[i] = W[o * C0IN + c];                 // transpose to [c][o]
    }
    __syncthreads();

    const int s   = blockIdx.x * 256 + threadIdx.x;
    const int b   = s >> 15;                      // / (M*K)
    const int rem = s & 32767;
    const int m   = rem >> 5;

    const int j = g_idx[s];
    const float* qp = q + ((size_t)b*MM + m)*3;
    const float* pp = p + ((size_t)b*NN + j)*3;
    const float f0 = pp[0] - qp[0];
    const float f1 = pp[1] - qp[1];
    const float f2 = pp[2] - qp[2];

    float4 acc[16];
    const float4* b4 = reinterpret_cast<const float4*>(bias);
#pragma unroll
    for (int i = 0; i < 16; i++) acc[i] = b4[i];

    const float4* W4 = reinterpret_cast<const float4*>(Wsm);
    rank1(acc, W4 + 0*16, f0);
    rank1(acc, W4 + 1*16, f1);
    rank1(acc, W4 + 2*16, f2);

    const float4* xr = reinterpret_cast<const float4*>(g_xT + (((size_t)b*NN + j) << 6));
#pragma unroll 1
    for (int c4 = 0; c4 < 16; c4++) {
        float4 xv = xr[c4];
        rank1(acc, W4 + (3 + 4*c4 + 0)*16, xv.x);
        rank1(acc, W4 + (3 + 4*c4 + 1)*16, xv.y);
        rank1(acc, W4 + (3 + 4*c4 + 2)*16, xv.z);
        rank1(acc, W4 + (3 + 4*c4 + 3)*16, xv.w);
    }

#pragma unroll
    for (int i = 0; i < 16; i++) {
        g_h0[(size_t)(4*i+0)*STOT + s] = acc[i].x;
        g_h0[(size_t)(4*i+1)*STOT + s] = acc[i].y;
        g_h0[(size_t)(4*i+2)*STOT + s] = acc[i].z;
        g_h0[(size_t)(4*i+3)*STOT + s] = acc[i].w;
    }
}

// ---------------- layers 1/2: BN(prev)+ReLU fused read, linear (64 -> 64) ---
__global__ void __launch_bounds__(256)
k_layer(const float* __restrict__ Hin, float* __restrict__ Hout,
        const float* __restrict__ W, const float* __restrict__ bias) {
    __shared__ float Wsm[64*64];
    __shared__ float scs[64], shs[64];
    const int co0 = blockIdx.y * 64;
    for (int i = threadIdx.x; i < 4096; i += 256) {
        int c = i >> 6, o = i & 63;
        Wsm[i] = W[(co0 + o)*64 + c];
    }
    if (threadIdx.x < 64) {
        scs[threadIdx.x] = g_scale[threadIdx.x];
        shs[threadIdx.x] = g_shift[threadIdx.x];
    }
    __syncthreads();

    const int s = blockIdx.x * 256 + threadIdx.x;
    float4 acc[16];
    const float4* b4 = reinterpret_cast<const float4*>(bias + co0);
#pragma unroll
    for (int i = 0; i < 16; i++) acc[i] = b4[i];

    const float4* W4 = reinterpret_cast<const float4*>(Wsm);
#pragma unroll 4
    for (int c = 0; c < 64; c++) {
        float v = Hin[(size_t)c*STOT + s];
        v = fmaxf(fmaf(v, scs[c], shs[c]), 0.0f);
        rank1(acc, W4 + c*16, v);
    }

#pragma unroll
    for (int i = 0; i < 16; i++) {
        Hout[(size_t)(co0 + 4*i+0)*STOT + s] = acc[i].x;
        Hout[(size_t)(co0 + 4*i+1)*STOT + s] = acc[i].y;
        Hout[(size_t)(co0 + 4*i+2)*STOT + s] = acc[i].z;
        Hout[(size_t)(co0 + 4*i+3)*STOT + s] = acc[i].w;
    }
}

// ---------------- per-channel partial sums (deterministic) ------------------
__global__ void k_stats(const float* __restrict__ H) {
    const int c   = blockIdx.y;
    const int blk = blockIdx.x;                    // 32 blocks per channel
    const int CHUNK = STOT / 32;                   // 8192
    const float4* base = reinterpret_cast<const float4*>(H + (size_t)c*STOT + (size_t)blk*CHUNK);
    float sum = 0.f, sq = 0.f;
#pragma unroll
    for (int i = threadIdx.x; i < CHUNK/4; i += 256) {
        float4 v = base[i];
        sum += v.x + v.y + v.z + v.w;
        sq  += v.x*v.x + v.y*v.y + v.z*v.z + v.w*v.w;
    }
#pragma unroll
    for (int d = 16; d; d >>= 1) {
        sum += __shfl_down_sync(0xffffffffu, sum, d);
        sq  += __shfl_down_sync(0xffffffffu, sq,  d);
    }
    __shared__ float ws[8], wq[8];
    int warp = threadIdx.x >> 5, lane = threadIdx.x & 31;
    if (lane == 0) { ws[warp] = sum; wq[warp] = sq; }
    __syncthreads();
    if (threadIdx.x == 0) {
        float a = 0.f, b2 = 0.f;
#pragma unroll
        for (int w = 0; w < 8; w++) { a += ws[w]; b2 += wq[w]; }
        g_psum[c*32 + blk] = a;
        g_psq [c*32 + blk] = b2;
    }
}

// ---------------- finalize mean/var -> scale/shift ---------------------------
__global__ void k_reduce(const float* __restrict__ gam, const float* __restrict__ bet) {
    const int c = blockIdx.x;
    const int lane = threadIdx.x;   // 32 threads
    float sum = g_psum[c*32 + lane];
    float sq  = g_psq [c*32 + lane];
#pragma unroll
    for (int d = 16; d; d >>= 1) {
        sum += __shfl_down_sync(0xffffffffu, sum, d);
        sq  += __shfl_down_sync(0xffffffffu, sq,  d);
    }
    if (lane == 0) {
        const float inv = 1.0f / (float)STOT;
        float mu  = sum * inv;
        float var = sq * inv - mu * mu;
        float sc  = gam[c] * rsqrtf(var + EPSBN);
        g_scale[c] = sc;
        g_shift[c] = bet[c] - mu * sc;
    }
}

// ---------------- BN+ReLU + max over K -> out (B,C2,M) ----------------------
__global__ void k_maxpool(float* __restrict__ out) {
    const int t = blockIdx.x * 256 + threadIdx.x;   // B*C2*M threads exactly
    const int m = t & 1023;
    const int c = (t >> 10) & 127;
    const int b = t >> 17;
    const size_t s0 = (((size_t)b*MM) + m) * KK;
    const float4* hp = reinterpret_cast<const float4*>(g_h2 + (size_t)c*STOT + s0);
    const float sc = g_scale[c], sh = g_shift[c];
    float vmax = 0.0f;    // relu outputs are >= 0
#pragma unroll
    for (int i = 0; i < 8; i++) {
        float4 v = hp[i];
        vmax = fmaxf(vmax, fmaf(v.x, sc, sh));
        vmax = fmaxf(vmax, fmaf(v.y, sc, sh));
        vmax = fmaxf(vmax, fmaf(v.z, sc, sh));
        vmax = fmaxf(vmax, fmaf(v.w, sc, sh));
    }
    out[(size_t)BB*MM*3 + (((size_t)b*C2 + c) << 10) + m] = vmax;
}

// ---------------- launch ------------------------------------------------------
extern "C" void kernel_launch(void* const* d_in, const int* in_sizes, int n_in,
                              void* d_out, int out_size) {
    const float* p   = (const float*)d_in[0];
    const float* q   = (const float*)d_in[1];
    const float* x   = (const float*)d_in[2];
    const float* W0  = (const float*)d_in[3];
    const float* b0  = (const float*)d_in[4];
    const float* g0  = (const float*)d_in[5];
    const float* be0 = (const float*)d_in[6];
    const float* W1  = (const float*)d_in[7];
    const float* b1  = (const float*)d_in[8];
    const float* g1  = (const float*)d_in[9];
    const float* be1 = (const float*)d_in[10];
    const float* W2  = (const float*)d_in[11];
    const float* b2  = (const float*)d_in[12];
    const float* g2  = (const float*)d_in[13];
    const float* be2 = (const float*)d_in[14];
    float* out = (float*)d_out;

    float *h0p, *h1p, *h2p;
    cudaGetSymbolAddress((void**)&h0p, g_h0);
    cudaGetSymbolAddress((void**)&h1p, g_h1);
    cudaGetSymbolAddress((void**)&h2p, g_h2);

    const int bq_smem = NN*3*4 + 8*KK*4;   // 50176 bytes
    cudaFuncSetAttribute(k_ballquery, cudaFuncAttributeMaxDynamicSharedMemorySize, bq_smem);

    k_transpose<<<dim3(NN/32, CF/32, BB), dim3(32, 8)>>>(x);
    k_copyq<<<(BB*MM*3)/256, 256>>>(q, out);
    k_ballquery<<<dim3(MM/8, BB), 256, bq_smem>>>(p, q);

    k_layer0<<<STOT/256, 256>>>(p, q, W0, b0);
    k_stats<<<dim3(32, C0), 256>>>(h0p);
    k_reduce<<<C0, 32>>>(g0, be0);

    k_layer<<<dim3(STOT/256, 1), 256>>>(h0p, h1p, W1, b1);
    k_stats<<<dim3(32, C1), 256>>>(h1p);
    k_reduce<<<C1, 32>>>(g1, be1);

    k_layer<<<dim3(STOT/256, 2), 256>>>(h1p, h2p, W2, b2);
    k_stats<<<dim3(32, C2), 256>>>(h2p);
    k_reduce<<<C2, 32>>>(g2, be2);

    k_maxpool<<<(BB*C2*MM)/256, 256>>>(out);
}

// round 2
// speedup vs baseline: 1.0395x; 1.0395x over previous
#include <cuda_runtime.h>
#include <cstdint>

// Problem constants
#define BB 8
#define NN 4096
#define MM 1024
#define KK 32
#define CF 64
#define C0IN 67
#define C0 64
#define C1 64
#define C2 128
#define STOT (BB*MM*KK)          // 262144 samples
#define SHALF (STOT/2)           // 131072
#define EPSBN 1e-5f

typedef unsigned long long ull;

// ---------------- scratch (device globals; no cudaMalloc allowed) ----------
__device__ int   g_idx[STOT];
__device__ float g_xT[BB*NN*CF];            // x transposed to (B,N,C)
__device__ float g_h0[(size_t)C0*STOT];     // pre-BN layer0 out, [C][S]
__device__ float g_h1[(size_t)C1*STOT];
__device__ float g_h2[(size_t)C2*STOT];
__device__ float g_psum[C2*32];
__device__ float g_psq [C2*32];
__device__ float g_scale[C2];
__device__ float g_shift[C2];

// ---------------- f32x2 packed helpers --------------------------------------
__device__ __forceinline__ ull ffma2(ull a, ull b, ull c) {
    ull d;
    asm("fma.rn.f32x2 %0, %1, %2, %3;" : "=l"(d) : "l"(a), "l"(b), "l"(c));
    return d;
}
__device__ __forceinline__ ull pack2(float v) {
    ull d; asm("mov.b64 %0, {%1, %1};" : "=l"(d) : "f"(v)); return d;
}
__device__ __forceinline__ ull pack2f(float x, float y) {
    ull d; asm("mov.b64 %0, {%1, %2};" : "=l"(d) : "f"(x), "f"(y)); return d;
}
__device__ __forceinline__ void unpack2(ull a, float& x, float& y) {
    asm("mov.b64 {%0, %1}, %2;" : "=f"(x), "=f"(y) : "l"(a));
}

// ---------------- transpose x: (B,C,N) -> (B,N,C) --------------------------
__global__ void k_transpose(const float* __restrict__ x) {
    __shared__ float t[32][33];
    int b  = blockIdx.z;
    int c0 = blockIdx.y * 32;
    int n0 = blockIdx.x * 32;
    int tx = threadIdx.x, ty = threadIdx.y;
#pragma unroll
    for (int r = ty; r < 32; r += 8)
        t[r][tx] = x[(size_t)b*CF*NN + (size_t)(c0 + r)*NN + n0 + tx];
    __syncthreads();
#pragma unroll
    for (int r = ty; r < 32; r += 8)
        g_xT[((size_t)b*NN + n0 + r)*CF + c0 + tx] = t[tx][r];
}

// ---------------- copy q into the head of d_out -----------------------------
__global__ void k_copyq(const float* __restrict__ q, float* __restrict__ out) {
    int i = blockIdx.x * 256 + threadIdx.x;   // exactly 24576 threads launched
    out[i] = q[i];
}

// ---------------- ball query ------------------------------------------------
__global__ void k_ballquery(const float* __restrict__ p, const float* __restrict__ q) {
    extern __shared__ float sp[];                 // NN*3 floats
    int* sfound = (int*)(sp + NN*3);              // [8][KK]
    const int b    = blockIdx.y;
    const int warp = threadIdx.x >> 5;
    const int lane = threadIdx.x & 31;
    const int m    = blockIdx.x * 8 + warp;

    const float* pb = p + (size_t)b * NN * 3;
    for (int i = threadIdx.x; i < NN*3; i += blockDim.x) sp[i] = pb[i];
    __syncthreads();

    const float qx = q[((size_t)b*MM + m)*3 + 0];
    const float qy = q[((size_t)b*MM + m)*3 + 1];
    const float qz = q[((size_t)b*MM + m)*3 + 2];
    const float R2 = 0.04f;

    int cnt = 0;
    for (int j0 = 0; j0 < NN; j0 += 32) {
        int j = j0 + lane;
        float dx = __fadd_rn(sp[3*j+0], -qx);
        float dy = __fadd_rn(sp[3*j+1], -qy);
        float dz = __fadd_rn(sp[3*j+2], -qz);
        float d2 = __fadd_rn(__fadd_rn(__fmul_rn(dx,dx), __fmul_rn(dy,dy)), __fmul_rn(dz,dz));
        bool in = d2 < R2;
        unsigned bal = __ballot_sync(0xffffffffu, in);
        if (in) {
            int slot = cnt + __popc(bal & ((1u << lane) - 1u));
            if (slot < KK) sfound[warp*KK + slot] = j;
        }
        cnt += __popc(bal);
        if (cnt >= KK) break;
    }
    __syncwarp();
    int v;
    if (lane < cnt)      v = sfound[warp*KK + lane];
    else if (cnt > 0)    v = sfound[warp*KK];
    else                 v = 0;
    g_idx[((size_t)b*MM + m)*KK + lane] = v;
}

// ---------------- layer 0: gather + linear (67 -> 32-out group) -------------
// 2 samples per thread (s, s+SHALF), 32 output channels per blockIdx.y group.
__global__ void __launch_bounds__(256, 2)
k_layer0(const float* __restrict__ p, const float* __restrict__ q,
         const float* __restrict__ W, const float* __restrict__ bias) {
    __shared__ __align__(16) float Wsm[C0IN * 32];
    const int co0 = blockIdx.y * 32;
    for (int i = threadIdx.x; i < C0IN*32; i += 256) {
        int c = i >> 5, o = i & 31;
        Wsm[i] = W[(co0 + o) * C0IN + c];         // [c][o]
    }
    __syncthreads();

    const int s0 = blockIdx.x * 256 + threadIdx.x;
    const int s1 = s0 + SHALF;

    // gather geometry for both samples
    float f[2][3];
    const float* xr[2];
    {
        const int ss[2] = {s0, s1};
#pragma unroll
        for (int t = 0; t < 2; t++) {
            int s = ss[t];
            int b = s >> 15;
            int m = (s & 32767) >> 5;
            int j = g_idx[s];
            const float* qp = q + ((size_t)b*MM + m)*3;
            const float* pp = p + ((size_t)b*NN + j)*3;
            f[t][0] = pp[0] - qp[0];
            f[t][1] = pp[1] - qp[1];
            f[t][2] = pp[2] - qp[2];
            xr[t] = g_xT + (((size_t)b*NN + j) << 6);
        }
    }

    ull acc0[16], acc1[16];
    {
        const float2* b2 = reinterpret_cast<const float2*>(bias + co0);
#pragma unroll
        for (int k = 0; k < 16; k++) {
            float2 bv = b2[k];
            ull bb = pack2f(bv.x, bv.y);
            acc0[k] = bb; acc1[k] = bb;
        }
    }

    // geometric channels 0..2
#pragma unroll
    for (int c = 0; c < 3; c++) {
        ull p0 = pack2(f[0][c]), p1 = pack2(f[1][c]);
        const ulonglong2* wr = reinterpret_cast<const ulonglong2*>(Wsm + (c << 5));
#pragma unroll
        for (int k = 0; k < 8; k++) {
            ulonglong2 w = wr[k];
            acc0[2*k]   = ffma2(p0, w.x, acc0[2*k]);
            acc0[2*k+1] = ffma2(p0, w.y, acc0[2*k+1]);
            acc1[2*k]   = ffma2(p1, w.x, acc1[2*k]);
            acc1[2*k+1] = ffma2(p1, w.y, acc1[2*k+1]);
        }
    }

    // feature channels 3..66, x gathered per sample
    const float4* x40 = reinterpret_cast<const float4*>(xr[0]);
    const float4* x41 = reinterpret_cast<const float4*>(xr[1]);
#pragma unroll 2
    for (int c4 = 0; c4 < 16; c4++) {
        float4 v0 = x40[c4];
        float4 v1 = x41[c4];
        float a0[4] = {v0.x, v0.y, v0.z, v0.w};
        float a1[4] = {v1.x, v1.y, v1.z, v1.w};
#pragma unroll
        for (int cc = 0; cc < 4; cc++) {
            int c = 3 + 4*c4 + cc;
            ull p0 = pack2(a0[cc]), p1 = pack2(a1[cc]);
            const ulonglong2* wr = reinterpret_cast<const ulonglong2*>(Wsm + (c << 5));
#pragma unroll
            for (int k = 0; k < 8; k++) {
                ulonglong2 w = wr[k];
                acc0[2*k]   = ffma2(p0, w.x, acc0[2*k]);
                acc0[2*k+1] = ffma2(p0, w.y, acc0[2*k+1]);
                acc1[2*k]   = ffma2(p1, w.x, acc1[2*k]);
                acc1[2*k+1] = ffma2(p1, w.y, acc1[2*k+1]);
            }
        }
    }

#pragma unroll
    for (int k = 0; k < 16; k++) {
        float x0, y0, x1, y1;
        unpack2(acc0[k], x0, y0);
        unpack2(acc1[k], x1, y1);
        g_h0[(size_t)(co0 + 2*k+0)*STOT + s0] = x0;
        g_h0[(size_t)(co0 + 2*k+1)*STOT + s0] = y0;
        g_h0[(size_t)(co0 + 2*k+0)*STOT + s1] = x1;
        g_h0[(size_t)(co0 + 2*k+1)*STOT + s1] = y1;
    }
}

// ---------------- layers 1/2: BN(prev)+ReLU fused read, 64-in -> 32-out ----
__global__ void __launch_bounds__(256, 2)
k_layer(const float* __restrict__ Hin, float* __restrict__ Hout,
        const float* __restrict__ W, const float* __restrict__ bias) {
    __shared__ __align__(16) float Wsm[64 * 32];
    __shared__ float scs[64], shs[64];
    const int co0 = blockIdx.y * 32;
    for (int i = threadIdx.x; i < 64*32; i += 256) {
        int c = i >> 5, o = i & 31;
        Wsm[i] = W[(co0 + o)*64 + c];
    }
    if (threadIdx.x < 64) {
        scs[threadIdx.x] = g_scale[threadIdx.x];
        shs[threadIdx.x] = g_shift[threadIdx.x];
    }
    __syncthreads();

    const int s0 = blockIdx.x * 256 + threadIdx.x;
    const int s1 = s0 + SHALF;

    ull acc0[16], acc1[16];
    {
        const float2* b2 = reinterpret_cast<const float2*>(bias + co0);
#pragma unroll
        for (int k = 0; k < 16; k++) {
            float2 bv = b2[k];
            ull bb = pack2f(bv.x, bv.y);
            acc0[k] = bb; acc1[k] = bb;
        }
    }

#pragma unroll 4
    for (int c = 0; c < 64; c++) {
        float sc = scs[c], sh = shs[c];
        float v0 = fmaxf(fmaf(Hin[(size_t)c*STOT + s0], sc, sh), 0.0f);
        float v1 = fmaxf(fmaf(Hin[(size_t)c*STOT + s1], sc, sh), 0.0f);
        ull p0 = pack2(v0), p1 = pack2(v1);
        const ulonglong2* wr = reinterpret_cast<const ulonglong2*>(Wsm + (c << 5));
#pragma unroll
        for (int k = 0; k < 8; k++) {
            ulonglong2 w = wr[k];
            acc0[2*k]   = ffma2(p0, w.x, acc0[2*k]);
            acc0[2*k+1] = ffma2(p0, w.y, acc0[2*k+1]);
            acc1[2*k]   = ffma2(p1, w.x, acc1[2*k]);
            acc1[2*k+1] = ffma2(p1, w.y, acc1[2*k+1]);
        }
    }

#pragma unroll
    for (int k = 0; k < 16; k++) {
        float x0, y0, x1, y1;
        unpack2(acc0[k], x0, y0);
        unpack2(acc1[k], x1, y1);
        Hout[(size_t)(co0 + 2*k+0)*STOT + s0] = x0;
        Hout[(size_t)(co0 + 2*k+1)*STOT + s0] = y0;
        Hout[(size_t)(co0 + 2*k+0)*STOT + s1] = x1;
        Hout[(size_t)(co0 + 2*k+1)*STOT + s1] = y1;
    }
}

// ---------------- per-channel partial sums (deterministic) ------------------
__global__ void k_stats(const float* __restrict__ H) {
    const int c   = blockIdx.y;
    const int blk = blockIdx.x;                    // 32 blocks per channel
    const int CHUNK = STOT / 32;                   // 8192
    const float4* base = reinterpret_cast<const float4*>(H + (size_t)c*STOT + (size_t)blk*CHUNK);
    float sum = 0.f, sq = 0.f;
#pragma unroll
    for (int i = threadIdx.x; i < CHUNK/4; i += 256) {
        float4 v = base[i];
        sum += v.x + v.y + v.z + v.w;
        sq  += v.x*v.x + v.y*v.y + v.z*v.z + v.w*v.w;
    }
#pragma unroll
    for (int d = 16; d; d >>= 1) {
        sum += __shfl_down_sync(0xffffffffu, sum, d);
        sq  += __shfl_down_sync(0xffffffffu, sq,  d);
    }
    __shared__ float ws[8], wq[8];
    int warp = threadIdx.x >> 5, lane = threadIdx.x & 31;
    if (lane == 0) { ws[warp] = sum; wq[warp] = sq; }
    __syncthreads();
    if (threadIdx.x == 0) {
        float a = 0.f, b2 = 0.f;
#pragma unroll
        for (int w = 0; w < 8; w++) { a += ws[w]; b2 += wq[w]; }
        g_psum[c*32 + blk] = a;
        g_psq [c*32 + blk] = b2;
    }
}

// ---------------- finalize mean/var -> scale/shift ---------------------------
__global__ void k_reduce(const float* __restrict__ gam, const float* __restrict__ bet) {
    const int c = blockIdx.x;
    const int lane = threadIdx.x;   // 32 threads
    float sum = g_psum[c*32 + lane];
    float sq  = g_psq [c*32 + lane];
#pragma unroll
    for (int d = 16; d; d >>= 1) {
        sum += __shfl_down_sync(0xffffffffu, sum, d);
        sq  += __shfl_down_sync(0xffffffffu, sq,  d);
    }
    if (lane == 0) {
        const float inv = 1.0f / (float)STOT;
        float mu  = sum * inv;
        float var = sq * inv - mu * mu;
        float sc  = gam[c] * rsqrtf(var + EPSBN);
        g_scale[c] = sc;
        g_shift[c] = bet[c] - mu * sc;
    }
}

// ---------------- BN+ReLU + max over K -> out (B,C2,M) ----------------------
__global__ void k_maxpool(float* __restrict__ out) {
    const int t = blockIdx.x * 256 + threadIdx.x;   // B*C2*M threads exactly
    const int m = t & 1023;
    const int c = (t >> 10) & 127;
    const int b = t >> 17;
    const size_t s0 = (((size_t)b*MM) + m) * KK;
    const float4* hp = reinterpret_cast<const float4*>(g_h2 + (size_t)c*STOT + s0);
    const float sc = g_scale[c], sh = g_shift[c];
    float vmax = 0.0f;
#pragma unroll
    for (int i = 0; i < 8; i++) {
        float4 v = hp[i];
        vmax = fmaxf(vmax, fmaf(v.x, sc, sh));
        vmax = fmaxf(vmax, fmaf(v.y, sc, sh));
        vmax = fmaxf(vmax, fmaf(v.z, sc, sh));
        vmax = fmaxf(vmax, fmaf(v.w, sc, sh));
    }
    out[(size_t)BB*MM*3 + (((size_t)b*C2 + c) << 10) + m] = vmax;
}

// ---------------- launch ------------------------------------------------------
extern "C" void kernel_launch(void* const* d_in, const int* in_sizes, int n_in,
                              void* d_out, int out_size) {
    const float* p   = (const float*)d_in[0];
    const float* q   = (const float*)d_in[1];
    const float* x   = (const float*)d_in[2];
    const float* W0  = (const float*)d_in[3];
    const float* b0  = (const float*)d_in[4];
    const float* g0  = (const float*)d_in[5];
    const float* be0 = (const float*)d_in[6];
    const float* W1  = (const float*)d_in[7];
    const float* b1  = (const float*)d_in[8];
    const float* g1  = (const float*)d_in[9];
    const float* be1 = (const float*)d_in[10];
    const float* W2  = (const float*)d_in[11];
    const float* b2  = (const float*)d_in[12];
    const float* g2  = (const float*)d_in[13];
    const float* be2 = (const float*)d_in[14];
    float* out = (float*)d_out;

    float *h0p, *h1p, *h2p;
    cudaGetSymbolAddress((void**)&h0p, g_h0);
    cudaGetSymbolAddress((void**)&h1p, g_h1);
    cudaGetSymbolAddress((void**)&h2p, g_h2);

    const int bq_smem = NN*3*4 + 8*KK*4;   // 50176 bytes
    cudaFuncSetAttribute(k_ballquery, cudaFuncAttributeMaxDynamicSharedMemorySize, bq_smem);

    k_transpose<<<dim3(NN/32, CF/32, BB), dim3(32, 8)>>>(x);
    k_copyq<<<(BB*MM*3)/256, 256>>>(q, out);
    k_ballquery<<<dim3(MM/8, BB), 256, bq_smem>>>(p, q);

    k_layer0<<<dim3(SHALF/256, 2), 256>>>(p, q, W0, b0);
    k_stats<<<dim3(32, C0), 256>>>(h0p);
    k_reduce<<<C0, 32>>>(g0, be0);

    k_layer<<<dim3(SHALF/256, 2), 256>>>(h0p, h1p, W1, b1);
    k_stats<<<dim3(32, C1), 256>>>(h1p);
    k_reduce<<<C1, 32>>>(g1, be1);

    k_layer<<<dim3(SHALF/256, 4), 256>>>(h1p, h2p, W2, b2);
    k_stats<<<dim3(32, C2), 256>>>(h2p);
    k_reduce<<<C2, 32>>>(g2, be2);

    k_maxpool<<<(BB*C2*MM)/256, 256>>>(out);
}

// round 3
// speedup vs baseline: 1.2717x; 1.2234x over previous
#include <cuda_runtime.h>
#include <cstdint>

#define BB 8
#define NN 4096
#define MM 1024
#define KK 32
#define CF 64
#define C0IN 67
#define C0 64
#define C1 64
#define C2 128
#define STOT (BB*MM*KK)          // 262144
#define EPSBN 1e-5f
#define BLKS 256                 // samples per block tile

typedef unsigned long long ull;

// ---------------- scratch ----------------------------------------------------
__device__ int   g_idx[STOT];
__device__ float g_xT[BB*NN*CF];
__device__ float g_h0[(size_t)C0*STOT];
__device__ float g_h1[(size_t)C1*STOT];
__device__ float g_h2[(size_t)C2*STOT];
__device__ float g_psum[C2*32];
__device__ float g_psq [C2*32];
__device__ float g_scale[C2];
__device__ float g_shift[C2];

// ---------------- f32x2 helpers ----------------------------------------------
__device__ __forceinline__ ull ffma2(ull a, ull b, ull c) {
    ull d;
    asm("fma.rn.f32x2 %0, %1, %2, %3;" : "=l"(d) : "l"(a), "l"(b), "l"(c));
    return d;
}
__device__ __forceinline__ ull pack2f(float x, float y) {
    ull d; asm("mov.b64 %0, {%1, %2};" : "=l"(d) : "f"(x), "f"(y)); return d;
}

// ---------------- transpose x: (B,C,N) -> (B,N,C) ----------------------------
__global__ void k_transpose(const float* __restrict__ x) {
    __shared__ float t[32][33];
    int b  = blockIdx.z;
    int c0 = blockIdx.y * 32;
    int n0 = blockIdx.x * 32;
    int tx = threadIdx.x, ty = threadIdx.y;
#pragma unroll
    for (int r = ty; r < 32; r += 8)
        t[r][tx] = x[(size_t)b*CF*NN + (size_t)(c0 + r)*NN + n0 + tx];
    __syncthreads();
#pragma unroll
    for (int r = ty; r < 32; r += 8)
        g_xT[((size_t)b*NN + n0 + r)*CF + c0 + tx] = t[tx][r];
}

__global__ void k_copyq(const float* __restrict__ q, float* __restrict__ out) {
    int i = blockIdx.x * 256 + threadIdx.x;
    out[i] = q[i];
}

// ---------------- ball query --------------------------------------------------
__global__ void k_ballquery(const float* __restrict__ p, const float* __restrict__ q) {
    extern __shared__ float sp[];
    int* sfound = (int*)(sp + NN*3);
    const int b    = blockIdx.y;
    const int warp = threadIdx.x >> 5;
    const int lane = threadIdx.x & 31;
    const int m    = blockIdx.x * 8 + warp;

    const float* pb = p + (size_t)b * NN * 3;
    for (int i = threadIdx.x; i < NN*3; i += blockDim.x) sp[i] = pb[i];
    __syncthreads();

    const float qx = q[((size_t)b*MM + m)*3 + 0];
    const float qy = q[((size_t)b*MM + m)*3 + 1];
    const float qz = q[((size_t)b*MM + m)*3 + 2];
    const float R2 = 0.04f;

    int cnt = 0;
    for (int j0 = 0; j0 < NN; j0 += 32) {
        int j = j0 + lane;
        float dx = __fadd_rn(sp[3*j+0], -qx);
        float dy = __fadd_rn(sp[3*j+1], -qy);
        float dz = __fadd_rn(sp[3*j+2], -qz);
        float d2 = __fadd_rn(__fadd_rn(__fmul_rn(dx,dx), __fmul_rn(dy,dy)), __fmul_rn(dz,dz));
        bool in = d2 < R2;
        unsigned bal = __ballot_sync(0xffffffffu, in);
        if (in) {
            int slot = cnt + __popc(bal & ((1u << lane) - 1u));
            if (slot < KK) sfound[warp*KK + slot] = j;
        }
        cnt += __popc(bal);
        if (cnt >= KK) break;
    }
    __syncwarp();
    int v;
    if (lane < cnt)      v = sfound[warp*KK + lane];
    else if (cnt > 0)    v = sfound[warp*KK];
    else                 v = 0;
    g_idx[((size_t)b*MM + m)*KK + lane] = v;
}

// =====================================================================
// Register-blocked GEMM layers: block tile = 64 outs x 256 samples.
// Thread micro-tile: 8 outs x 4 f32x2 sample-pairs (8 samples).
// Weights pre-packed {w,w} in SMEM; inputs staged in SMEM.
// =====================================================================

// ---------------- layer 0: gather + (67 -> 64) -------------------------------
__global__ void __launch_bounds__(256, 2)
k_layer0(const float* __restrict__ p, const float* __restrict__ q,
         const float* __restrict__ W, const float* __restrict__ bias) {
    extern __shared__ char smemraw[];
    ull*   Wsm = (ull*)smemraw;                 // [67][64] packed
    float* Ism = (float*)(Wsm + C0IN*64);       // [67][256]

    const int tid = threadIdx.x;
    const int sBase = blockIdx.x * BLKS;

    // stage packed weights
    for (int i = tid; i < C0IN*64; i += 256) {
        int c = i >> 6, o = i & 63;
        float w = W[o * C0IN + c];
        Wsm[i] = pack2f(w, w);
    }

    // stage gathered input tile (no BN on layer0 input)
    {
        const int s = sBase + tid;
        const int b = s >> 15;
        const int m = (s & 32767) >> 5;
        const int j = g_idx[s];
        const float* qp = q + ((size_t)b*MM + m)*3;
        const float* pp = p + ((size_t)b*NN + j)*3;
        Ism[0*BLKS + tid] = pp[0] - qp[0];
        Ism[1*BLKS + tid] = pp[1] - qp[1];
        Ism[2*BLKS + tid] = pp[2] - qp[2];
        const float4* xr = reinterpret_cast<const float4*>(g_xT + (((size_t)b*NN + j) << 6));
#pragma unroll
        for (int c4 = 0; c4 < 16; c4++) {
            float4 v = xr[c4];
            Ism[(3 + 4*c4 + 0)*BLKS + tid] = v.x;
            Ism[(3 + 4*c4 + 1)*BLKS + tid] = v.y;
            Ism[(3 + 4*c4 + 2)*BLKS + tid] = v.z;
            Ism[(3 + 4*c4 + 3)*BLKS + tid] = v.w;
        }
    }
    __syncthreads();

    const int og = tid >> 5;          // 0..7 -> output group of 8
    const int sg = tid & 31;          // 0..31 -> sample-pair group of 4
    const int o_base = og * 8;
    const int sp_base = sg * 4;

    ull acc[8][4];
#pragma unroll
    for (int o = 0; o < 8; o++) {
        float bv = bias[o_base + o];
        ull bb = pack2f(bv, bv);
#pragma unroll
        for (int sp = 0; sp < 4; sp++) acc[o][sp] = bb;
    }

#pragma unroll 2
    for (int c = 0; c < C0IN; c++) {
        const ull* ir = reinterpret_cast<const ull*>(Ism + c*BLKS) + sp_base;
        ull i0 = ir[0], i1 = ir[1], i2 = ir[2], i3 = ir[3];
        const ull* wr = Wsm + c*64 + o_base;
#pragma unroll
        for (int o = 0; o < 8; o++) {
            ull w = wr[o];
            acc[o][0] = ffma2(i0, w, acc[o][0]);
            acc[o][1] = ffma2(i1, w, acc[o][1]);
            acc[o][2] = ffma2(i2, w, acc[o][2]);
            acc[o][3] = ffma2(i3, w, acc[o][3]);
        }
    }

#pragma unroll
    for (int o = 0; o < 8; o++) {
        ull* op = reinterpret_cast<ull*>(g_h0 + (size_t)(o_base + o)*STOT + sBase) + sp_base;
        *reinterpret_cast<ulonglong2*>(op)     = make_ulonglong2(acc[o][0], acc[o][1]);
        *reinterpret_cast<ulonglong2*>(op + 2) = make_ulonglong2(acc[o][2], acc[o][3]);
    }
}

// ---------------- layers 1/2: BN+ReLU on input, (64 -> 64-out group) ---------
__global__ void __launch_bounds__(256, 2)
k_layer(const float* __restrict__ Hin, float* __restrict__ Hout,
        const float* __restrict__ W, const float* __restrict__ bias) {
    extern __shared__ char smemraw[];
    ull*   Wsm = (ull*)smemraw;                 // [64][64] packed
    float* Ism = (float*)(Wsm + 64*64);         // [64][256]
    __shared__ float scs[64], shs[64];

    const int tid = threadIdx.x;
    const int co0 = blockIdx.y * 64;
    const int sBase = blockIdx.x * BLKS;

    if (tid < 64) {
        scs[tid] = g_scale[tid];
        shs[tid] = g_shift[tid];
    }
    for (int i = tid; i < 64*64; i += 256) {
        int c = i >> 6, o = i & 63;
        float w = W[(co0 + o)*64 + c];
        Wsm[i] = pack2f(w, w);
    }
    __syncthreads();

    // stage BN+ReLU'd input tile
    for (int i = tid; i < 64*64; i += 256) {
        int c = i >> 6, s4 = i & 63;
        float4 v = *reinterpret_cast<const float4*>(Hin + (size_t)c*STOT + sBase + s4*4);
        float sc = scs[c], sh = shs[c];
        v.x = fmaxf(fmaf(v.x, sc, sh), 0.0f);
        v.y = fmaxf(fmaf(v.y, sc, sh), 0.0f);
        v.z = fmaxf(fmaf(v.z, sc, sh), 0.0f);
        v.w = fmaxf(fmaf(v.w, sc, sh), 0.0f);
        *reinterpret_cast<float4*>(Ism + c*BLKS + s4*4) = v;
    }
    __syncthreads();

    const int og = tid >> 5;
    const int sg = tid & 31;
    const int o_base = og * 8;
    const int sp_base = sg * 4;

    ull acc[8][4];
#pragma unroll
    for (int o = 0; o < 8; o++) {
        float bv = bias[co0 + o_base + o];
        ull bb = pack2f(bv, bv);
#pragma unroll
        for (int sp = 0; sp < 4; sp++) acc[o][sp] = bb;
    }

#pragma unroll 2
    for (int c = 0; c < 64; c++) {
        const ull* ir = reinterpret_cast<const ull*>(Ism + c*BLKS) + sp_base;
        ull i0 = ir[0], i1 = ir[1], i2 = ir[2], i3 = ir[3];
        const ull* wr = Wsm + c*64 + o_base;
#pragma unroll
        for (int o = 0; o < 8; o++) {
            ull w = wr[o];
            acc[o][0] = ffma2(i0, w, acc[o][0]);
            acc[o][1] = ffma2(i1, w, acc[o][1]);
            acc[o][2] = ffma2(i2, w, acc[o][2]);
            acc[o][3] = ffma2(i3, w, acc[o][3]);
        }
    }

#pragma unroll
    for (int o = 0; o < 8; o++) {
        ull* op = reinterpret_cast<ull*>(Hout + (size_t)(co0 + o_base + o)*STOT + sBase) + sp_base;
        *reinterpret_cast<ulonglong2*>(op)     = make_ulonglong2(acc[o][0], acc[o][1]);
        *reinterpret_cast<ulonglong2*>(op + 2) = make_ulonglong2(acc[o][2], acc[o][3]);
    }
}

// ---------------- per-channel partial sums (deterministic) -------------------
__global__ void k_stats(const float* __restrict__ H) {
    const int c   = blockIdx.y;
    const int blk = blockIdx.x;
    const int CHUNK = STOT / 32;
    const float4* base = reinterpret_cast<const float4*>(H + (size_t)c*STOT + (size_t)blk*CHUNK);
    float sum = 0.f, sq = 0.f;
#pragma unroll
    for (int i = threadIdx.x; i < CHUNK/4; i += 256) {
        float4 v = base[i];
        sum += v.x + v.y + v.z + v.w;
        sq  += v.x*v.x + v.y*v.y + v.z*v.z + v.w*v.w;
    }
#pragma unroll
    for (int d = 16; d; d >>= 1) {
        sum += __shfl_down_sync(0xffffffffu, sum, d);
        sq  += __shfl_down_sync(0xffffffffu, sq,  d);
    }
    __shared__ float ws[8], wq[8];
    int warp = threadIdx.x >> 5, lane = threadIdx.x & 31;
    if (lane == 0) { ws[warp] = sum; wq[warp] = sq; }
    __syncthreads();
    if (threadIdx.x == 0) {
        float a = 0.f, b2 = 0.f;
#pragma unroll
        for (int w = 0; w < 8; w++) { a += ws[w]; b2 += wq[w]; }
        g_psum[c*32 + blk] = a;
        g_psq [c*32 + blk] = b2;
    }
}

__global__ void k_reduce(const float* __restrict__ gam, const float* __restrict__ bet) {
    const int c = blockIdx.x;
    const int lane = threadIdx.x;
    float sum = g_psum[c*32 + lane];
    float sq  = g_psq [c*32 + lane];
#pragma unroll
    for (int d = 16; d; d >>= 1) {
        sum += __shfl_down_sync(0xffffffffu, sum, d);
        sq  += __shfl_down_sync(0xffffffffu, sq,  d);
    }
    if (lane == 0) {
        const float inv = 1.0f / (float)STOT;
        float mu  = sum * inv;
        float var = sq * inv - mu * mu;
        float sc  = gam[c] * rsqrtf(var + EPSBN);
        g_scale[c] = sc;
        g_shift[c] = bet[c] - mu * sc;
    }
}

// ---------------- BN+ReLU + max over K -> out (B,C2,M) -----------------------
__global__ void k_maxpool(float* __restrict__ out) {
    const int t = blockIdx.x * 256 + threadIdx.x;
    const int m = t & 1023;
    const int c = (t >> 10) & 127;
    const int b = t >> 17;
    const size_t s0 = (((size_t)b*MM) + m) * KK;
    const float4* hp = reinterpret_cast<const float4*>(g_h2 + (size_t)c*STOT + s0);
    const float sc = g_scale[c], sh = g_shift[c];
    float vmax = 0.0f;
#pragma unroll
    for (int i = 0; i < 8; i++) {
        float4 v = hp[i];
        vmax = fmaxf(vmax, fmaf(v.x, sc, sh));
        vmax = fmaxf(vmax, fmaf(v.y, sc, sh));
        vmax = fmaxf(vmax, fmaf(v.z, sc, sh));
        vmax = fmaxf(vmax, fmaf(v.w, sc, sh));
    }
    out[(size_t)BB*MM*3 + (((size_t)b*C2 + c) << 10) + m] = vmax;
}

// ---------------- launch -------------------------------------------------------
extern "C" void kernel_launch(void* const* d_in, const int* in_sizes, int n_in,
                              void* d_out, int out_size) {
    const float* p   = (const float*)d_in[0];
    const float* q   = (const float*)d_in[1];
    const float* x   = (const float*)d_in[2];
    const float* W0  = (const float*)d_in[3];
    const float* b0  = (const float*)d_in[4];
    const float* g0  = (const float*)d_in[5];
    const float* be0 = (const float*)d_in[6];
    const float* W1  = (const float*)d_in[7];
    const float* b1  = (const float*)d_in[8];
    const float* g1  = (const float*)d_in[9];
    const float* be1 = (const float*)d_in[10];
    const float* W2  = (const float*)d_in[11];
    const float* b2  = (const float*)d_in[12];
    const float* g2  = (const float*)d_in[13];
    const float* be2 = (const float*)d_in[14];
    float* out = (float*)d_out;

    float *h0p, *h1p, *h2p;
    cudaGetSymbolAddress((void**)&h0p, g_h0);
    cudaGetSymbolAddress((void**)&h1p, g_h1);
    cudaGetSymbolAddress((void**)&h2p, g_h2);

    const int bq_smem = NN*3*4 + 8*KK*4;
    const int l0_smem = C0IN*64*8 + C0IN*BLKS*4;   // 102912
    const int l_smem  = 64*64*8   + 64*BLKS*4;     // 98304
    cudaFuncSetAttribute(k_ballquery, cudaFuncAttributeMaxDynamicSharedMemorySize, bq_smem);
    cudaFuncSetAttribute(k_layer0, cudaFuncAttributeMaxDynamicSharedMemorySize, l0_smem);
    cudaFuncSetAttribute(k_layer,  cudaFuncAttributeMaxDynamicSharedMemorySize, l_smem);

    k_transpose<<<dim3(NN/32, CF/32, BB), dim3(32, 8)>>>(x);
    k_copyq<<<(BB*MM*3)/256, 256>>>(q, out);
    k_ballquery<<<dim3(MM/8, BB), 256, bq_smem>>>(p, q);

    k_layer0<<<STOT/BLKS, 256, l0_smem>>>(p, q, W0, b0);
    k_stats<<<dim3(32, C0), 256>>>(h0p);
    k_reduce<<<C0, 32>>>(g0, be0);

    k_layer<<<dim3(STOT/BLKS, 1), 256, l_smem>>>(h0p, h1p, W1, b1);
    k_stats<<<dim3(32, C1), 256>>>(h1p);
    k_reduce<<<C1, 32>>>(g1, be1);

    k_layer<<<dim3(STOT/BLKS, 2), 256, l_smem>>>(h1p, h2p, W2, b2);
    k_stats<<<dim3(32, C2), 256>>>(h2p);
    k_reduce<<<C2, 32>>>(g2, be2);

    k_maxpool<<<(BB*C2*MM)/256, 256>>>(out);
}

// round 4
// speedup vs baseline: 1.4179x; 1.1150x over previous
#include <cuda_runtime.h>
#include <cstdint>

#define BB 8
#define NN 4096
#define MM 1024
#define KK 32
#define CF 64
#define C0IN 67
#define C0 64
#define C1 64
#define C2 128
#define STOT (BB*MM*KK)          // 262144
#define NBLK (STOT/256)          // 1024 sample-blocks
#define EPSBN 1e-5f
#define BLKS 256

typedef unsigned long long ull;

// ---------------- scratch ----------------------------------------------------
__device__ int   g_idx[STOT];
__device__ float g_xT[BB*NN*CF];
__device__ float g_h0[(size_t)C0*STOT];
__device__ float g_h1[(size_t)C1*STOT];
__device__ float g_h2[(size_t)C2*STOT];
__device__ float g_ps1[(size_t)C2*NBLK];
__device__ float g_ps2[(size_t)C2*NBLK];
__device__ float g_scale[C2];
__device__ float g_shift[C2];

// ---------------- f32x2 helpers ----------------------------------------------
__device__ __forceinline__ ull ffma2(ull a, ull b, ull c) {
    ull d;
    asm("fma.rn.f32x2 %0, %1, %2, %3;" : "=l"(d) : "l"(a), "l"(b), "l"(c));
    return d;
}
__device__ __forceinline__ ull pack2f(float x, float y) {
    ull d; asm("mov.b64 %0, {%1, %2};" : "=l"(d) : "f"(x), "f"(y)); return d;
}
__device__ __forceinline__ void unpack2(ull a, float& x, float& y) {
    asm("mov.b64 {%0, %1}, %2;" : "=f"(x), "=f"(y) : "l"(a));
}

// ---------------- transpose x: (B,C,N) -> (B,N,C) ----------------------------
__global__ void k_transpose(const float* __restrict__ x) {
    __shared__ float t[32][33];
    int b  = blockIdx.z;
    int c0 = blockIdx.y * 32;
    int n0 = blockIdx.x * 32;
    int tx = threadIdx.x, ty = threadIdx.y;
#pragma unroll
    for (int r = ty; r < 32; r += 8)
        t[r][tx] = x[(size_t)b*CF*NN + (size_t)(c0 + r)*NN + n0 + tx];
    __syncthreads();
#pragma unroll
    for (int r = ty; r < 32; r += 8)
        g_xT[((size_t)b*NN + n0 + r)*CF + c0 + tx] = t[tx][r];
}

__global__ void k_copyq(const float* __restrict__ q, float* __restrict__ out) {
    int i = blockIdx.x * 256 + threadIdx.x;
    out[i] = q[i];
}

// ---------------- ball query --------------------------------------------------
__global__ void k_ballquery(const float* __restrict__ p, const float* __restrict__ q) {
    extern __shared__ float sp[];
    int* sfound = (int*)(sp + NN*3);
    const int b    = blockIdx.y;
    const int warp = threadIdx.x >> 5;
    const int lane = threadIdx.x & 31;
    const int m    = blockIdx.x * 8 + warp;

    const float* pb = p + (size_t)b * NN * 3;
    for (int i = threadIdx.x; i < NN*3; i += blockDim.x) sp[i] = pb[i];
    __syncthreads();

    const float qx = q[((size_t)b*MM + m)*3 + 0];
    const float qy = q[((size_t)b*MM + m)*3 + 1];
    const float qz = q[((size_t)b*MM + m)*3 + 2];
    const float R2 = 0.04f;

    int cnt = 0;
    for (int j0 = 0; j0 < NN; j0 += 32) {
        int j = j0 + lane;
        float dx = __fadd_rn(sp[3*j+0], -qx);
        float dy = __fadd_rn(sp[3*j+1], -qy);
        float dz = __fadd_rn(sp[3*j+2], -qz);
        float d2 = __fadd_rn(__fadd_rn(__fmul_rn(dx,dx), __fmul_rn(dy,dy)), __fmul_rn(dz,dz));
        bool in = d2 < R2;
        unsigned bal = __ballot_sync(0xffffffffu, in);
        if (in) {
            int slot = cnt + __popc(bal & ((1u << lane) - 1u));
            if (slot < KK) sfound[warp*KK + slot] = j;
        }
        cnt += __popc(bal);
        if (cnt >= KK) break;
    }
    __syncwarp();
    int v;
    if (lane < cnt)      v = sfound[warp*KK + lane];
    else if (cnt > 0)    v = sfound[warp*KK];
    else                 v = 0;
    g_idx[((size_t)b*MM + m)*KK + lane] = v;
}

// =====================================================================
// GEMM core: block = 64 outs x 256 samples; thread = 8 outs x 8 samples
// (two conflict-free 16B sample groups). Weights {w,w}-duplicated in
// SMEM, warp-uniform broadcast loads. Epilogue: store + fused BN stats.
// =====================================================================

__device__ __forceinline__ void gemm_core_epilogue(
    const ull* __restrict__ Wsm, const float* __restrict__ Ism, int Cin,
    const float* __restrict__ bias, float* __restrict__ Hout,
    int co0, int sBase, int bx)
{
    const int tid = threadIdx.x;
    const int og = tid >> 5;
    const int sg = tid & 31;
    const int o_base = og * 8;

    ull acc[8][4];
#pragma unroll
    for (int o = 0; o < 8; o++) {
        float bv = bias[co0 + o_base + o];
        ull bb = pack2f(bv, bv);
        acc[o][0] = bb; acc[o][1] = bb; acc[o][2] = bb; acc[o][3] = bb;
    }

#pragma unroll 2
    for (int c = 0; c < Cin; c++) {
        const ulonglong2* ip = reinterpret_cast<const ulonglong2*>(Ism + c*BLKS);
        ulonglong2 ia = ip[sg];        // samples 4sg .. 4sg+3
        ulonglong2 ib = ip[32 + sg];   // samples 128+4sg ..
        const ull* wr = Wsm + c*64 + o_base;   // warp-uniform broadcast
#pragma unroll
        for (int o = 0; o < 8; o++) {
            ull w = wr[o];
            acc[o][0] = ffma2(ia.x, w, acc[o][0]);
            acc[o][1] = ffma2(ia.y, w, acc[o][1]);
            acc[o][2] = ffma2(ib.x, w, acc[o][2]);
            acc[o][3] = ffma2(ib.y, w, acc[o][3]);
        }
    }

#pragma unroll
    for (int o = 0; o < 8; o++) {
        const int ch = co0 + o_base + o;
        ull* row = reinterpret_cast<ull*>(Hout + (size_t)ch*STOT + sBase);
        reinterpret_cast<ulonglong2*>(row)[sg]      = make_ulonglong2(acc[o][0], acc[o][1]);
        reinterpret_cast<ulonglong2*>(row + 64)[sg] = make_ulonglong2(acc[o][2], acc[o][3]);

        float f0,f1,f2,f3,f4,f5,f6,f7;
        unpack2(acc[o][0], f0, f1);
        unpack2(acc[o][1], f2, f3);
        unpack2(acc[o][2], f4, f5);
        unpack2(acc[o][3], f6, f7);
        float s = ((f0+f1)+(f2+f3)) + ((f4+f5)+(f6+f7));
        float qq = ((f0*f0+f1*f1)+(f2*f2+f3*f3)) + ((f4*f4+f5*f5)+(f6*f6+f7*f7));
#pragma unroll
        for (int d = 16; d; d >>= 1) {
            s  += __shfl_down_sync(0xffffffffu, s,  d);
            qq += __shfl_down_sync(0xffffffffu, qq, d);
        }
        if (sg == 0) {
            g_ps1[(size_t)ch*NBLK + bx] = s;
            g_ps2[(size_t)ch*NBLK + bx] = qq;
        }
    }
}

// ---------------- layer 0: gather + (67 -> 64) --------------------------------
__global__ void __launch_bounds__(256, 2)
k_layer0(const float* __restrict__ p, const float* __restrict__ q,
         const float* __restrict__ W, const float* __restrict__ bias) {
    extern __shared__ char smemraw[];
    ull*   Wsm = (ull*)smemraw;                 // [67][64] {w,w}
    float* Ism = (float*)(Wsm + C0IN*64);       // [67][256]

    const int tid = threadIdx.x;
    const int sBase = blockIdx.x * BLKS;

    for (int i = tid; i < C0IN*64; i += 256) {
        int c = i >> 6, o = i & 63;
        float w = W[o * C0IN + c];
        Wsm[i] = pack2f(w, w);
    }
    {
        const int s = sBase + tid;
        const int b = s >> 15;
        const int m = (s & 32767) >> 5;
        const int j = g_idx[s];
        const float* qp = q + ((size_t)b*MM + m)*3;
        const float* pp = p + ((size_t)b*NN + j)*3;
        Ism[0*BLKS + tid] = pp[0] - qp[0];
        Ism[1*BLKS + tid] = pp[1] - qp[1];
        Ism[2*BLKS + tid] = pp[2] - qp[2];
        const float4* xr = reinterpret_cast<const float4*>(g_xT + (((size_t)b*NN + j) << 6));
#pragma unroll
        for (int c4 = 0; c4 < 16; c4++) {
            float4 v = xr[c4];
            Ism[(3 + 4*c4 + 0)*BLKS + tid] = v.x;
            Ism[(3 + 4*c4 + 1)*BLKS + tid] = v.y;
            Ism[(3 + 4*c4 + 2)*BLKS + tid] = v.z;
            Ism[(3 + 4*c4 + 3)*BLKS + tid] = v.w;
        }
    }
    __syncthreads();

    gemm_core_epilogue(Wsm, Ism, C0IN, bias, g_h0, 0, sBase, blockIdx.x);
}

// ---------------- layers 1/2: BN+ReLU staged input, (64 -> 64-out group) ------
__global__ void __launch_bounds__(256, 2)
k_layer(const float* __restrict__ Hin, float* __restrict__ Hout,
        const float* __restrict__ W, const float* __restrict__ bias) {
    extern __shared__ char smemraw[];
    ull*   Wsm = (ull*)smemraw;                 // [64][64] {w,w}
    float* Ism = (float*)(Wsm + 64*64);         // [64][256]
    __shared__ float scs[64], shs[64];

    const int tid = threadIdx.x;
    const int co0 = blockIdx.y * 64;
    const int sBase = blockIdx.x * BLKS;

    if (tid < 64) {
        scs[tid] = g_scale[tid];
        shs[tid] = g_shift[tid];
    }
    for (int i = tid; i < 64*64; i += 256) {
        int c = i >> 6, o = i & 63;
        float w = W[(co0 + o)*64 + c];
        Wsm[i] = pack2f(w, w);
    }
    __syncthreads();

    for (int i = tid; i < 64*64; i += 256) {
        int c = i >> 6, s4 = i & 63;
        float4 v = *reinterpret_cast<const float4*>(Hin + (size_t)c*STOT + sBase + s4*4);
        float sc = scs[c], sh = shs[c];
        v.x = fmaxf(fmaf(v.x, sc, sh), 0.0f);
        v.y = fmaxf(fmaf(v.y, sc, sh), 0.0f);
        v.z = fmaxf(fmaf(v.z, sc, sh), 0.0f);
        v.w = fmaxf(fmaf(v.w, sc, sh), 0.0f);
        *reinterpret_cast<float4*>(Ism + c*BLKS + s4*4) = v;
    }
    __syncthreads();

    gemm_core_epilogue(Wsm, Ism, 64, bias, Hout, co0, sBase, blockIdx.x);
}

// ---------------- final stats reduce: 1024 partials -> scale/shift ------------
__global__ void k_reduce2(const float* __restrict__ gam, const float* __restrict__ bet) {
    __shared__ float s1[256], s2[256];
    const int c = blockIdx.x;
    const int t = threadIdx.x;
    const float* p1 = g_ps1 + (size_t)c*NBLK;
    const float* p2 = g_ps2 + (size_t)c*NBLK;
    float a = ((p1[t] + p1[t+256]) + (p1[t+512] + p1[t+768]));
    float b = ((p2[t] + p2[t+256]) + (p2[t+512] + p2[t+768]));
    s1[t] = a; s2[t] = b;
    __syncthreads();
#pragma unroll
    for (int d = 128; d; d >>= 1) {
        if (t < d) { s1[t] += s1[t+d]; s2[t] += s2[t+d]; }
        __syncthreads();
    }
    if (t == 0) {
        const float inv = 1.0f / (float)STOT;
        float mu  = s1[0] * inv;
        float var = s2[0] * inv - mu * mu;
        float sc  = gam[c] * rsqrtf(var + EPSBN);
        g_scale[c] = sc;
        g_shift[c] = bet[c] - mu * sc;
    }
}

// ---------------- BN+ReLU + max over K -> out (B,C2,M) ------------------------
__global__ void k_maxpool(float* __restrict__ out) {
    const int t = blockIdx.x * 256 + threadIdx.x;
    const int m = t & 1023;
    const int c = (t >> 10) & 127;
    const int b = t >> 17;
    const size_t s0 = (((size_t)b*MM) + m) * KK;
    const float4* hp = reinterpret_cast<const float4*>(g_h2 + (size_t)c*STOT + s0);
    const float sc = g_scale[c], sh = g_shift[c];
    float vmax = 0.0f;
#pragma unroll
    for (int i = 0; i < 8; i++) {
        float4 v = hp[i];
        vmax = fmaxf(vmax, fmaf(v.x, sc, sh));
        vmax = fmaxf(vmax, fmaf(v.y, sc, sh));
        vmax = fmaxf(vmax, fmaf(v.z, sc, sh));
        vmax = fmaxf(vmax, fmaf(v.w, sc, sh));
    }
    out[(size_t)BB*MM*3 + (((size_t)b*C2 + c) << 10) + m] = vmax;
}

// ---------------- launch --------------------------------------------------------
extern "C" void kernel_launch(void* const* d_in, const int* in_sizes, int n_in,
                              void* d_out, int out_size) {
    const float* p   = (const float*)d_in[0];
    const float* q   = (const float*)d_in[1];
    const float* x   = (const float*)d_in[2];
    const float* W0  = (const float*)d_in[3];
    const float* b0  = (const float*)d_in[4];
    const float* g0  = (const float*)d_in[5];
    const float* be0 = (const float*)d_in[6];
    const float* W1  = (const float*)d_in[7];
    const float* b1  = (const float*)d_in[8];
    const float* g1  = (const float*)d_in[9];
    const float* be1 = (const float*)d_in[10];
    const float* W2  = (const float*)d_in[11];
    const float* b2  = (const float*)d_in[12];
    const float* g2  = (const float*)d_in[13];
    const float* be2 = (const float*)d_in[14];
    float* out = (float*)d_out;

    float *h0p, *h1p, *h2p;
    cudaGetSymbolAddress((void**)&h0p, g_h0);
    cudaGetSymbolAddress((void**)&h1p, g_h1);
    cudaGetSymbolAddress((void**)&h2p, g_h2);

    const int bq_smem = NN*3*4 + 8*KK*4;
    const int l0_smem = C0IN*64*8 + C0IN*BLKS*4;   // 102912
    const int l_smem  = 64*64*8   + 64*BLKS*4;     // 98304
    cudaFuncSetAttribute(k_ballquery, cudaFuncAttributeMaxDynamicSharedMemorySize, bq_smem);
    cudaFuncSetAttribute(k_layer0, cudaFuncAttributeMaxDynamicSharedMemorySize, l0_smem);
    cudaFuncSetAttribute(k_layer,  cudaFuncAttributeMaxDynamicSharedMemorySize, l_smem);

    k_transpose<<<dim3(NN/32, CF/32, BB), dim3(32, 8)>>>(x);
    k_copyq<<<(BB*MM*3)/256, 256>>>(q, out);
    k_ballquery<<<dim3(MM/8, BB), 256, bq_smem>>>(p, q);

    k_layer0<<<NBLK, 256, l0_smem>>>(p, q, W0, b0);
    k_reduce2<<<C0, 256>>>(g0, be0);

    k_layer<<<dim3(NBLK, 1), 256, l_smem>>>(h0p, h1p, W1, b1);
    k_reduce2<<<C1, 256>>>(g1, be1);

    k_layer<<<dim3(NBLK, 2), 256, l_smem>>>(h1p, h2p, W2, b2);
    k_reduce2<<<C2, 256>>>(g2, be2);

    k_maxpool<<<(BB*C2*MM)/256, 256>>>(out);
}

// round 5
// speedup vs baseline: 1.6126x; 1.1373x over previous
#include <cuda_runtime.h>
#include <cstdint>

#define BB 8
#define NN 4096
#define MM 1024
#define KK 32
#define CF 64
#define C0IN 67
#define C0 64
#define C1 64
#define C2 128
#define STOT (BB*MM*KK)          // 262144
#define NBLK (STOT/256)          // 1024 sample-blocks
#define NQ   (BB*MM)             // 8192 queries
#define EPSBN 1e-5f
#define BLKS 256

typedef unsigned long long ull;

// ---------------- scratch ----------------------------------------------------
__device__ int   g_idx[STOT];
__device__ float g_xT[BB*NN*CF];
__device__ float g_h0[(size_t)C0*STOT];
__device__ float g_h1[(size_t)C1*STOT];
__device__ float g_ps1[(size_t)C2*NBLK];
__device__ float g_ps2[(size_t)C2*NBLK];
__device__ float g_hmax[(size_t)C2*NQ];
__device__ float g_hmin[(size_t)C2*NQ];
__device__ float g_scale[C2];
__device__ float g_shift[C2];

// ---------------- f32x2 helpers ----------------------------------------------
__device__ __forceinline__ ull ffma2(ull a, ull b, ull c) {
    ull d;
    asm("fma.rn.f32x2 %0, %1, %2, %3;" : "=l"(d) : "l"(a), "l"(b), "l"(c));
    return d;
}
__device__ __forceinline__ ull pack2f(float x, float y) {
    ull d; asm("mov.b64 %0, {%1, %2};" : "=l"(d) : "f"(x), "f"(y)); return d;
}
__device__ __forceinline__ void unpack2(ull a, float& x, float& y) {
    asm("mov.b64 {%0, %1}, %2;" : "=f"(x), "=f"(y) : "l"(a));
}

// ---------------- transpose x: (B,C,N) -> (B,N,C) ----------------------------
__global__ void k_transpose(const float* __restrict__ x) {
    __shared__ float t[32][33];
    int b  = blockIdx.z;
    int c0 = blockIdx.y * 32;
    int n0 = blockIdx.x * 32;
    int tx = threadIdx.x, ty = threadIdx.y;
#pragma unroll
    for (int r = ty; r < 32; r += 8)
        t[r][tx] = x[(size_t)b*CF*NN + (size_t)(c0 + r)*NN + n0 + tx];
    __syncthreads();
#pragma unroll
    for (int r = ty; r < 32; r += 8)
        g_xT[((size_t)b*NN + n0 + r)*CF + c0 + tx] = t[tx][r];
}

__global__ void k_copyq(const float* __restrict__ q, float* __restrict__ out) {
    int i = blockIdx.x * 256 + threadIdx.x;
    out[i] = q[i];
}

// ---------------- ball query --------------------------------------------------
__global__ void k_ballquery(const float* __restrict__ p, const float* __restrict__ q) {
    extern __shared__ float sp[];
    int* sfound = (int*)(sp + NN*3);
    const int b    = blockIdx.y;
    const int warp = threadIdx.x >> 5;
    const int lane = threadIdx.x & 31;
    const int m    = blockIdx.x * 8 + warp;

    const float* pb = p + (size_t)b * NN * 3;
    for (int i = threadIdx.x; i < NN*3; i += blockDim.x) sp[i] = pb[i];
    __syncthreads();

    const float qx = q[((size_t)b*MM + m)*3 + 0];
    const float qy = q[((size_t)b*MM + m)*3 + 1];
    const float qz = q[((size_t)b*MM + m)*3 + 2];
    const float R2 = 0.04f;

    int cnt = 0;
    for (int j0 = 0; j0 < NN; j0 += 32) {
        int j = j0 + lane;
        float dx = __fadd_rn(sp[3*j+0], -qx);
        float dy = __fadd_rn(sp[3*j+1], -qy);
        float dz = __fadd_rn(sp[3*j+2], -qz);
        float d2 = __fadd_rn(__fadd_rn(__fmul_rn(dx,dx), __fmul_rn(dy,dy)), __fmul_rn(dz,dz));
        bool in = d2 < R2;
        unsigned bal = __ballot_sync(0xffffffffu, in);
        if (in) {
            int slot = cnt + __popc(bal & ((1u << lane) - 1u));
            if (slot < KK) sfound[warp*KK + slot] = j;
        }
        cnt += __popc(bal);
        if (cnt >= KK) break;
    }
    __syncwarp();
    int v;
    if (lane < cnt)      v = sfound[warp*KK + lane];
    else if (cnt > 0)    v = sfound[warp*KK];
    else                 v = 0;
    g_idx[((size_t)b*MM + m)*KK + lane] = v;
}

// =====================================================================
// GEMM core: block = 64 outs x 256 samples; thread = 8 outs x 8 samples.
// Inputs: 2 conflict-free LDS.128; weights: 4 LDS.128 broadcasts.
// =====================================================================

template<int CIN>
__device__ __forceinline__ void gemm_core(
    const ull* __restrict__ Wsm, const float* __restrict__ Ism,
    const float* __restrict__ bias, int co0, ull (&acc)[8][4])
{
    const int tid = threadIdx.x;
    const int og = tid >> 5;
    const int sg = tid & 31;
    const int o_base = og * 8;

#pragma unroll
    for (int o = 0; o < 8; o++) {
        float bv = bias[co0 + o_base + o];
        ull bb = pack2f(bv, bv);
        acc[o][0] = bb; acc[o][1] = bb; acc[o][2] = bb; acc[o][3] = bb;
    }

#pragma unroll 2
    for (int c = 0; c < CIN; c++) {
        const ulonglong2* ip = reinterpret_cast<const ulonglong2*>(Ism + c*BLKS);
        ulonglong2 ia = ip[sg];
        ulonglong2 ib = ip[32 + sg];
        const ulonglong2* wp = reinterpret_cast<const ulonglong2*>(Wsm + c*64 + o_base);
        ulonglong2 w01 = wp[0], w23 = wp[1], w45 = wp[2], w67 = wp[3];
        ull w[8] = {w01.x, w01.y, w23.x, w23.y, w45.x, w45.y, w67.x, w67.y};
#pragma unroll
        for (int o = 0; o < 8; o++) {
            acc[o][0] = ffma2(ia.x, w[o], acc[o][0]);
            acc[o][1] = ffma2(ia.y, w[o], acc[o][1]);
            acc[o][2] = ffma2(ib.x, w[o], acc[o][2]);
            acc[o][3] = ffma2(ib.y, w[o], acc[o][3]);
        }
    }
}

// epilogue: store h + BN partial stats
__device__ __forceinline__ void epi_store_stats(
    ull (&acc)[8][4], float* __restrict__ Hout, int co0, int sBase, int bx)
{
    const int tid = threadIdx.x;
    const int og = tid >> 5;
    const int sg = tid & 31;
    const int o_base = og * 8;

#pragma unroll
    for (int o = 0; o < 8; o++) {
        const int ch = co0 + o_base + o;
        ull* row = reinterpret_cast<ull*>(Hout + (size_t)ch*STOT + sBase);
        reinterpret_cast<ulonglong2*>(row)[sg]      = make_ulonglong2(acc[o][0], acc[o][1]);
        reinterpret_cast<ulonglong2*>(row + 64)[sg] = make_ulonglong2(acc[o][2], acc[o][3]);

        float f0,f1,f2,f3,f4,f5,f6,f7;
        unpack2(acc[o][0], f0, f1);
        unpack2(acc[o][1], f2, f3);
        unpack2(acc[o][2], f4, f5);
        unpack2(acc[o][3], f6, f7);
        float s = ((f0+f1)+(f2+f3)) + ((f4+f5)+(f6+f7));
        float qq = ((f0*f0+f1*f1)+(f2*f2+f3*f3)) + ((f4*f4+f5*f5)+(f6*f6+f7*f7));
#pragma unroll
        for (int d = 16; d; d >>= 1) {
            s  += __shfl_down_sync(0xffffffffu, s,  d);
            qq += __shfl_down_sync(0xffffffffu, qq, d);
        }
        if (sg == 0) {
            g_ps1[(size_t)ch*NBLK + bx] = s;
            g_ps2[(size_t)ch*NBLK + bx] = qq;
        }
    }
}

// epilogue: BN partial stats + per-query max/min (no h store)
__device__ __forceinline__ void epi_stats_maxmin(
    ull (&acc)[8][4], int co0, int bx)
{
    const int tid = threadIdx.x;
    const int og = tid >> 5;
    const int sg = tid & 31;
    const int o_base = og * 8;
    const int qa = sg >> 3;          // query 0..3 (samples 4sg..4sg+3)
    const int qb = 4 + qa;           // query 4..7 (samples 128+4sg..)

#pragma unroll
    for (int o = 0; o < 8; o++) {
        const int ch = co0 + o_base + o;
        float f0,f1,f2,f3,f4,f5,f6,f7;
        unpack2(acc[o][0], f0, f1);
        unpack2(acc[o][1], f2, f3);
        unpack2(acc[o][2], f4, f5);
        unpack2(acc[o][3], f6, f7);
        float s = ((f0+f1)+(f2+f3)) + ((f4+f5)+(f6+f7));
        float qq = ((f0*f0+f1*f1)+(f2*f2+f3*f3)) + ((f4*f4+f5*f5)+(f6*f6+f7*f7));
        float mxa = fmaxf(fmaxf(f0,f1), fmaxf(f2,f3));
        float mna = fminf(fminf(f0,f1), fminf(f2,f3));
        float mxb = fmaxf(fmaxf(f4,f5), fmaxf(f6,f7));
        float mnb = fminf(fminf(f4,f5), fminf(f6,f7));
#pragma unroll
        for (int d = 16; d; d >>= 1) {
            s  += __shfl_down_sync(0xffffffffu, s,  d);
            qq += __shfl_down_sync(0xffffffffu, qq, d);
        }
#pragma unroll
        for (int d = 4; d; d >>= 1) {
            mxa = fmaxf(mxa, __shfl_down_sync(0xffffffffu, mxa, d, 8));
            mna = fminf(mna, __shfl_down_sync(0xffffffffu, mna, d, 8));
            mxb = fmaxf(mxb, __shfl_down_sync(0xffffffffu, mxb, d, 8));
            mnb = fminf(mnb, __shfl_down_sync(0xffffffffu, mnb, d, 8));
        }
        if (sg == 0) {
            g_ps1[(size_t)ch*NBLK + bx] = s;
            g_ps2[(size_t)ch*NBLK + bx] = qq;
        }
        if ((sg & 7) == 0) {
            g_hmax[(size_t)ch*NQ + bx*8 + qa] = mxa;
            g_hmin[(size_t)ch*NQ + bx*8 + qa] = mna;
            g_hmax[(size_t)ch*NQ + bx*8 + qb] = mxb;
            g_hmin[(size_t)ch*NQ + bx*8 + qb] = mnb;
        }
    }
}

// ---------------- layer 0: gather + (67 -> 64) --------------------------------
__global__ void __launch_bounds__(256, 2)
k_layer0(const float* __restrict__ p, const float* __restrict__ q,
         const float* __restrict__ W, const float* __restrict__ bias) {
    extern __shared__ char smemraw[];
    ull*   Wsm = (ull*)smemraw;                 // [67][64] {w,w}
    float* Ism = (float*)(Wsm + C0IN*64);       // [67][256]

    const int tid = threadIdx.x;
    const int sBase = blockIdx.x * BLKS;

    for (int i = tid; i < C0IN*64; i += 256) {
        int c = i >> 6, o = i & 63;
        float w = W[o * C0IN + c];
        Wsm[i] = pack2f(w, w);
    }
    {
        const int s = sBase + tid;
        const int b = s >> 15;
        const int m = (s & 32767) >> 5;
        const int j = g_idx[s];
        const float* qp = q + ((size_t)b*MM + m)*3;
        const float* pp = p + ((size_t)b*NN + j)*3;
        Ism[0*BLKS + tid] = pp[0] - qp[0];
        Ism[1*BLKS + tid] = pp[1] - qp[1];
        Ism[2*BLKS + tid] = pp[2] - qp[2];
        const float4* xr = reinterpret_cast<const float4*>(g_xT + (((size_t)b*NN + j) << 6));
#pragma unroll
        for (int c4 = 0; c4 < 16; c4++) {
            float4 v = xr[c4];
            Ism[(3 + 4*c4 + 0)*BLKS + tid] = v.x;
            Ism[(3 + 4*c4 + 1)*BLKS + tid] = v.y;
            Ism[(3 + 4*c4 + 2)*BLKS + tid] = v.z;
            Ism[(3 + 4*c4 + 3)*BLKS + tid] = v.w;
        }
    }
    __syncthreads();

    ull acc[8][4];
    gemm_core<C0IN>(Wsm, Ism, bias, 0, acc);
    epi_store_stats(acc, g_h0, 0, sBase, blockIdx.x);
}

// ---------------- layers 1/2: BN+ReLU staged input, (64 -> 64-out group) ------
template<bool DO_MAX>
__global__ void __launch_bounds__(256, 2)
k_layer(const float* __restrict__ Hin, float* __restrict__ Hout,
        const float* __restrict__ W, const float* __restrict__ bias) {
    extern __shared__ char smemraw[];
    ull*   Wsm = (ull*)smemraw;                 // [64][64] {w,w}
    float* Ism = (float*)(Wsm + 64*64);         // [64][256]
    __shared__ float scs[64], shs[64];

    const int tid = threadIdx.x;
    const int co0 = blockIdx.y * 64;
    const int sBase = blockIdx.x * BLKS;

    if (tid < 64) {
        scs[tid] = g_scale[tid];
        shs[tid] = g_shift[tid];
    }
    for (int i = tid; i < 64*64; i += 256) {
        int c = i >> 6, o = i & 63;
        float w = W[(co0 + o)*64 + c];
        Wsm[i] = pack2f(w, w);
    }
    __syncthreads();

    for (int i = tid; i < 64*64; i += 256) {
        int c = i >> 6, s4 = i & 63;
        float4 v = *reinterpret_cast<const float4*>(Hin + (size_t)c*STOT + sBase + s4*4);
        float sc = scs[c], sh = shs[c];
        v.x = fmaxf(fmaf(v.x, sc, sh), 0.0f);
        v.y = fmaxf(fmaf(v.y, sc, sh), 0.0f);
        v.z = fmaxf(fmaf(v.z, sc, sh), 0.0f);
        v.w = fmaxf(fmaf(v.w, sc, sh), 0.0f);
        *reinterpret_cast<float4*>(Ism + c*BLKS + s4*4) = v;
    }
    __syncthreads();

    ull acc[8][4];
    gemm_core<64>(Wsm, Ism, bias, co0, acc);
    if (DO_MAX)
        epi_stats_maxmin(acc, co0, blockIdx.x);
    else
        epi_store_stats(acc, Hout, co0, sBase, blockIdx.x);
}

// ---------------- final stats reduce: 1024 partials -> scale/shift ------------
__global__ void k_reduce2(const float* __restrict__ gam, const float* __restrict__ bet) {
    __shared__ float s1[256], s2[256];
    const int c = blockIdx.x;
    const int t = threadIdx.x;
    const float* p1 = g_ps1 + (size_t)c*NBLK;
    const float* p2 = g_ps2 + (size_t)c*NBLK;
    float a = ((p1[t] + p1[t+256]) + (p1[t+512] + p1[t+768]));
    float b = ((p2[t] + p2[t+256]) + (p2[t+512] + p2[t+768]));
    s1[t] = a; s2[t] = b;
    __syncthreads();
#pragma unroll
    for (int d = 128; d; d >>= 1) {
        if (t < d) { s1[t] += s1[t+d]; s2[t] += s2[t+d]; }
        __syncthreads();
    }
    if (t == 0) {
        const float inv = 1.0f / (float)STOT;
        float mu  = s1[0] * inv;
        float var = s2[0] * inv - mu * mu;
        float sc  = gam[c] * rsqrtf(var + EPSBN);
        g_scale[c] = sc;
        g_shift[c] = bet[c] - mu * sc;
    }
}

// ---------------- finalize: affine extreme + relu -> out (B,C2,M) -------------
__global__ void k_finalmax(float* __restrict__ out) {
    const int t = blockIdx.x * 256 + threadIdx.x;   // B*C2*M
    const int m = t & 1023;
    const int c = (t >> 10) & 127;
    const int b = t >> 17;
    // query column in hmax layout: block bx = b*128 + (m>>3); qd = m&7
    const int col = ((b << 7) + (m >> 3)) * 8 + (m & 7);
    const float sc = g_scale[c], sh = g_shift[c];
    float ext = (sc >= 0.0f) ? g_hmax[(size_t)c*NQ + col] : g_hmin[(size_t)c*NQ + col];
    float v = fmaxf(fmaf(ext, sc, sh), 0.0f);
    out[(size_t)BB*MM*3 + (((size_t)b*C2 + c) << 10) + m] = v;
}

// ---------------- launch --------------------------------------------------------
extern "C" void kernel_launch(void* const* d_in, const int* in_sizes, int n_in,
                              void* d_out, int out_size) {
    const float* p   = (const float*)d_in[0];
    const float* q   = (const float*)d_in[1];
    const float* x   = (const float*)d_in[2];
    const float* W0  = (const float*)d_in[3];
    const float* b0  = (const float*)d_in[4];
    const float* g0  = (const float*)d_in[5];
    const float* be0 = (const float*)d_in[6];
    const float* W1  = (const float*)d_in[7];
    const float* b1  = (const float*)d_in[8];
    const float* g1  = (const float*)d_in[9];
    const float* be1 = (const float*)d_in[10];
    const float* W2  = (const float*)d_in[11];
    const float* b2  = (const float*)d_in[12];
    const float* g2  = (const float*)d_in[13];
    const float* be2 = (const float*)d_in[14];
    float* out = (float*)d_out;

    float *h0p, *h1p;
    cudaGetSymbolAddress((void**)&h0p, g_h0);
    cudaGetSymbolAddress((void**)&h1p, g_h1);

    const int bq_smem = NN*3*4 + 8*KK*4;
    const int l0_smem = C0IN*64*8 + C0IN*BLKS*4;   // 102912
    const int l_smem  = 64*64*8   + 64*BLKS*4;     // 98304
    cudaFuncSetAttribute(k_ballquery, cudaFuncAttributeMaxDynamicSharedMemorySize, bq_smem);
    cudaFuncSetAttribute(k_layer0, cudaFuncAttributeMaxDynamicSharedMemorySize, l0_smem);
    cudaFuncSetAttribute(k_layer<false>, cudaFuncAttributeMaxDynamicSharedMemorySize, l_smem);
    cudaFuncSetAttribute(k_layer<true>,  cudaFuncAttributeMaxDynamicSharedMemorySize, l_smem);

    k_transpose<<<dim3(NN/32, CF/32, BB), dim3(32, 8)>>>(x);
    k_copyq<<<(BB*MM*3)/256, 256>>>(q, out);
    k_ballquery<<<dim3(MM/8, BB), 256, bq_smem>>>(p, q);

    k_layer0<<<NBLK, 256, l0_smem>>>(p, q, W0, b0);
    k_reduce2<<<C0, 256>>>(g0, be0);

    k_layer<false><<<dim3(NBLK, 1), 256, l_smem>>>(h0p, h1p, W1, b1);
    k_reduce2<<<C1, 256>>>(g1, be1);

    k_layer<true><<<dim3(NBLK, 2), 256, l_smem>>>(h1p, nullptr, W2, b2);
    k_reduce2<<<C2, 256>>>(g2, be2);

    k_finalmax<<<(BB*C2*MM)/256, 256>>>(out);
}